// round 1
// baseline (speedup 1.0000x reference)
#include <cuda_runtime.h>

#define BATCH 8
#define HEADS 8
#define SEQ 4096
#define DMODEL 512
#define DEPTH 64
#define PROJ 256
#define ROWS (BATCH*SEQ)

// Scratch (allocation-free rule: __device__ globals)
__device__ float g_q[BATCH*HEADS*SEQ*DEPTH];
__device__ float g_k[BATCH*HEADS*SEQ*DEPTH];
__device__ float g_v[BATCH*HEADS*SEQ*DEPTH];
__device__ float g_kp[BATCH*HEADS*PROJ*DEPTH];
__device__ float g_vp[BATCH*HEADS*PROJ*DEPTH];
__device__ float g_ao[ROWS*DMODEL];

// ---------------------------------------------------------------------------
// Kernel 1: fused QKV projection.  C3 = x @ {wq,wk,wv}; epilogue scatters to
// head-major [b,h,n,d] scratch.  64x64 tile, BK=16, 4x4 per-thread, 3 outputs.
// ---------------------------------------------------------------------------
__global__ __launch_bounds__(256) void k_qkv(const float* __restrict__ x,
                                             const float* __restrict__ wq,
                                             const float* __restrict__ wk,
                                             const float* __restrict__ wv)
{
    __shared__ float As[16][64];
    __shared__ float Bq[16][64];
    __shared__ float Bk[16][64];
    __shared__ float Bv[16][64];
    const int tid  = threadIdx.x;
    const int row0 = blockIdx.y * 64;
    const int col0 = blockIdx.x * 64;
    const int tx = tid & 15, ty = tid >> 4;
    const int aRow = tid >> 2, aK = (tid & 3) << 2;
    const int bRow = tid >> 4, bCol = (tid & 15) << 2;
    float cq[4][4] = {}, ck[4][4] = {}, cv[4][4] = {};

    for (int k0 = 0; k0 < DMODEL; k0 += 16) {
        float4 av = *(const float4*)&x[(row0 + aRow) * DMODEL + k0 + aK];
        As[aK+0][aRow] = av.x; As[aK+1][aRow] = av.y;
        As[aK+2][aRow] = av.z; As[aK+3][aRow] = av.w;
        *(float4*)&Bq[bRow][bCol] = *(const float4*)&wq[(k0+bRow)*DMODEL + col0 + bCol];
        *(float4*)&Bk[bRow][bCol] = *(const float4*)&wk[(k0+bRow)*DMODEL + col0 + bCol];
        *(float4*)&Bv[bRow][bCol] = *(const float4*)&wv[(k0+bRow)*DMODEL + col0 + bCol];
        __syncthreads();
        #pragma unroll
        for (int kk = 0; kk < 16; kk++) {
            float4 a4 = *(float4*)&As[kk][ty<<2];
            float4 q4 = *(float4*)&Bq[kk][tx<<2];
            float4 k4 = *(float4*)&Bk[kk][tx<<2];
            float4 v4 = *(float4*)&Bv[kk][tx<<2];
            float a[4]  = {a4.x, a4.y, a4.z, a4.w};
            float qb[4] = {q4.x, q4.y, q4.z, q4.w};
            float kb[4] = {k4.x, k4.y, k4.z, k4.w};
            float vb[4] = {v4.x, v4.y, v4.z, v4.w};
            #pragma unroll
            for (int i = 0; i < 4; i++)
                #pragma unroll
                for (int j = 0; j < 4; j++) {
                    cq[i][j] += a[i]*qb[j];
                    ck[i][j] += a[i]*kb[j];
                    cv[i][j] += a[i]*vb[j];
                }
        }
        __syncthreads();
    }

    #pragma unroll
    for (int i = 0; i < 4; i++) {
        int gr = row0 + (ty<<2) + i;
        int b = gr >> 12, n = gr & (SEQ-1);
        #pragma unroll
        for (int j = 0; j < 4; j++) {
            int gc = col0 + (tx<<2) + j;
            int h = gc >> 6, d = gc & 63;
            int o = ((b*HEADS + h)*SEQ + n)*DEPTH + d;
            g_q[o] = cq[i][j];
            g_k[o] = ck[i][j];
            g_v[o] = cv[i][j];
        }
    }
}

// ---------------------------------------------------------------------------
// Kernel 2: low-rank projection.  kp[b,h,r,d] = sum_n E[h,n,r] * k[b,h,n,d]
// (and vp from F,v).  GEMM M=256(r), N=64(d), K=4096(n).
// grid = (4 r-tiles, 2 which, 64 bh)
// ---------------------------------------------------------------------------
__global__ __launch_bounds__(256) void k_proj(const float* __restrict__ E,
                                              const float* __restrict__ F)
{
    const int bh    = blockIdx.z;
    const int h     = bh & 7;
    const int which = blockIdx.y;
    const int r0    = blockIdx.x * 64;
    const float* A  = (which ? F : E) + h * SEQ * PROJ;
    const float* Bm = (which ? g_v : g_k) + bh * SEQ * DEPTH;
    float*       C  = (which ? g_vp : g_kp) + bh * PROJ * DEPTH;

    __shared__ float As[16][64];   // [n_local][r_local]
    __shared__ float Bs[16][64];   // [n_local][d]
    const int tid = threadIdx.x;
    const int tx = tid & 15, ty = tid >> 4;
    const int lRow = tid >> 4, lCol = (tid & 15) << 2;
    float c[4][4] = {};

    for (int k0 = 0; k0 < SEQ; k0 += 16) {
        *(float4*)&As[lRow][lCol] = *(const float4*)&A[(k0+lRow)*PROJ + r0 + lCol];
        *(float4*)&Bs[lRow][lCol] = *(const float4*)&Bm[(k0+lRow)*DEPTH + lCol];
        __syncthreads();
        #pragma unroll
        for (int kk = 0; kk < 16; kk++) {
            float4 a4 = *(float4*)&As[kk][ty<<2];
            float4 b4 = *(float4*)&Bs[kk][tx<<2];
            float a[4]  = {a4.x, a4.y, a4.z, a4.w};
            float bb[4] = {b4.x, b4.y, b4.z, b4.w};
            #pragma unroll
            for (int i = 0; i < 4; i++)
                #pragma unroll
                for (int j = 0; j < 4; j++)
                    c[i][j] += a[i]*bb[j];
        }
        __syncthreads();
    }
    #pragma unroll
    for (int i = 0; i < 4; i++)
        #pragma unroll
        for (int j = 0; j < 4; j++)
            C[(r0 + (ty<<2) + i)*DEPTH + (tx<<2) + j] = c[i][j];
}

// ---------------------------------------------------------------------------
// Kernel 3: fused attention.  Per (bh, 64-row tile):
//   S = Q @ Kp^T * scale; P = softmax(S); O = P @ Vp; scatter O to concat layout.
// SMEM: sQ[64][64] | sKpT[64][256] (reused as sP[64][256]) | sVp[256][64]
// GEMM1: 8 warps, each owns 8 rows x 256 cols (8x8/thread), softmax = shfl.
// GEMM2: 16x16 threads, 4x4/thread.
// ---------------------------------------------------------------------------
__global__ __launch_bounds__(256) void k_attn()
{
    extern __shared__ float sm[];
    float* sQ   = sm;                 // 4096 floats
    float* sKpT = sm + 4096;          // 16384 floats  (reused as sP)
    float* sVp  = sm + 4096 + 16384;  // 16384 floats

    const int bh = blockIdx.y;
    const int m0 = blockIdx.x * 64;
    const float* Q  = g_q  + bh * SEQ * DEPTH + m0 * DEPTH;
    const float* Kp = g_kp + bh * PROJ * DEPTH;
    const float* Vp = g_vp + bh * PROJ * DEPTH;
    const int tid = threadIdx.x;

    // Stage Q (contiguous 64x64 tile) and Vp (contiguous 256x64)
    for (int i = tid; i < 1024; i += 256)
        *(float4*)&sQ[i*4] = *(const float4*)&Q[i*4];
    for (int i = tid; i < 4096; i += 256)
        *(float4*)&sVp[i*4] = *(const float4*)&Vp[i*4];
    // Stage Kp transposed: thread tid owns row j=tid -> writes column j (conflict-free)
    {
        const int j = tid;
        #pragma unroll
        for (int d0 = 0; d0 < DEPTH; d0 += 4) {
            float4 kv = *(const float4*)&Kp[j*DEPTH + d0];
            sKpT[(d0+0)*PROJ + j] = kv.x;
            sKpT[(d0+1)*PROJ + j] = kv.y;
            sKpT[(d0+2)*PROJ + j] = kv.z;
            sKpT[(d0+3)*PROJ + j] = kv.w;
        }
    }
    __syncthreads();

    // GEMM1: S[64][256], warp wy owns rows wy*8..wy*8+7; lane holds cols lane+32*jj
    const int wy = tid >> 5, lane = tid & 31;
    float s[8][8];
    #pragma unroll
    for (int i = 0; i < 8; i++)
        #pragma unroll
        for (int jj = 0; jj < 8; jj++) s[i][jj] = 0.f;

    for (int kk = 0; kk < DEPTH; kk++) {
        float a[8], bv[8];
        #pragma unroll
        for (int i = 0; i < 8; i++)  a[i]  = sQ[(wy*8+i)*DEPTH + kk];     // broadcast
        #pragma unroll
        for (int jj = 0; jj < 8; jj++) bv[jj] = sKpT[kk*PROJ + lane + 32*jj]; // conflict-free
        #pragma unroll
        for (int i = 0; i < 8; i++)
            #pragma unroll
            for (int jj = 0; jj < 8; jj++)
                s[i][jj] += a[i]*bv[jj];
    }

    // Softmax per row (warp-local: full row lives in one warp)
    const float scale = 0.125f;   // 1/sqrt(64)
    float p[8][8];
    #pragma unroll
    for (int i = 0; i < 8; i++) {
        float mx = -1e30f;
        #pragma unroll
        for (int jj = 0; jj < 8; jj++) { s[i][jj] *= scale; mx = fmaxf(mx, s[i][jj]); }
        #pragma unroll
        for (int off = 16; off > 0; off >>= 1)
            mx = fmaxf(mx, __shfl_xor_sync(0xffffffff, mx, off));
        float sum = 0.f;
        #pragma unroll
        for (int jj = 0; jj < 8; jj++) { p[i][jj] = __expf(s[i][jj] - mx); sum += p[i][jj]; }
        #pragma unroll
        for (int off = 16; off > 0; off >>= 1)
            sum += __shfl_xor_sync(0xffffffff, sum, off);
        float inv = 1.0f / sum;
        #pragma unroll
        for (int jj = 0; jj < 8; jj++) p[i][jj] *= inv;
    }

    __syncthreads();          // everyone done reading sKpT
    float* sP = sKpT;         // reuse
    #pragma unroll
    for (int i = 0; i < 8; i++)
        #pragma unroll
        for (int jj = 0; jj < 8; jj++)
            sP[(wy*8+i)*PROJ + lane + 32*jj] = p[i][jj];
    __syncthreads();

    // GEMM2: O[64][64] = P[64][256] @ Vp[256][64]
    const int ty2 = tid >> 4, tx2 = tid & 15;
    float o[4][4] = {};
    #pragma unroll 4
    for (int kk = 0; kk < PROJ; kk++) {
        float a[4];
        #pragma unroll
        for (int i = 0; i < 4; i++) a[i] = sP[(ty2*4+i)*PROJ + kk];  // broadcast
        float4 b4 = *(float4*)&sVp[kk*DEPTH + tx2*4];
        float bb[4] = {b4.x, b4.y, b4.z, b4.w};
        #pragma unroll
        for (int i = 0; i < 4; i++)
            #pragma unroll
            for (int j = 0; j < 4; j++)
                o[i][j] += a[i]*bb[j];
    }

    const int b = bh >> 3, h = bh & 7;
    #pragma unroll
    for (int i = 0; i < 4; i++) {
        int n = m0 + ty2*4 + i;
        #pragma unroll
        for (int j = 0; j < 4; j++)
            g_ao[(b*SEQ + n)*DMODEL + h*DEPTH + tx2*4 + j] = o[i][j];
    }
}

// ---------------------------------------------------------------------------
// Kernel 4: output projection.  out = ao @ w_out + b_out
// ---------------------------------------------------------------------------
__global__ __launch_bounds__(256) void k_out(const float* __restrict__ w,
                                             const float* __restrict__ bias,
                                             float* __restrict__ out)
{
    __shared__ float As[16][64];
    __shared__ float Bs[16][64];
    const int tid  = threadIdx.x;
    const int row0 = blockIdx.y * 64;
    const int col0 = blockIdx.x * 64;
    const int tx = tid & 15, ty = tid >> 4;
    const int aRow = tid >> 2, aK = (tid & 3) << 2;
    const int bRow = tid >> 4, bCol = (tid & 15) << 2;
    float c[4][4] = {};

    for (int k0 = 0; k0 < DMODEL; k0 += 16) {
        float4 av = *(const float4*)&g_ao[(row0 + aRow) * DMODEL + k0 + aK];
        As[aK+0][aRow] = av.x; As[aK+1][aRow] = av.y;
        As[aK+2][aRow] = av.z; As[aK+3][aRow] = av.w;
        *(float4*)&Bs[bRow][bCol] = *(const float4*)&w[(k0+bRow)*DMODEL + col0 + bCol];
        __syncthreads();
        #pragma unroll
        for (int kk = 0; kk < 16; kk++) {
            float4 a4 = *(float4*)&As[kk][ty<<2];
            float4 b4 = *(float4*)&Bs[kk][tx<<2];
            float a[4]  = {a4.x, a4.y, a4.z, a4.w};
            float bb[4] = {b4.x, b4.y, b4.z, b4.w};
            #pragma unroll
            for (int i = 0; i < 4; i++)
                #pragma unroll
                for (int j = 0; j < 4; j++)
                    c[i][j] += a[i]*bb[j];
        }
        __syncthreads();
    }
    #pragma unroll
    for (int i = 0; i < 4; i++) {
        int gr = row0 + (ty<<2) + i;
        #pragma unroll
        for (int j = 0; j < 4; j++) {
            int gc = col0 + (tx<<2) + j;
            out[gr*DMODEL + gc] = c[i][j] + bias[gc];
        }
    }
}

// ---------------------------------------------------------------------------
extern "C" void kernel_launch(void* const* d_in, const int* in_sizes, int n_in,
                              void* d_out, int out_size)
{
    (void)in_sizes; (void)n_in; (void)out_size;
    const float* x     = (const float*)d_in[0];
    const float* wq    = (const float*)d_in[1];
    const float* wk    = (const float*)d_in[2];
    const float* wv    = (const float*)d_in[3];
    const float* E     = (const float*)d_in[4];
    const float* F     = (const float*)d_in[5];
    const float* w_out = (const float*)d_in[6];
    const float* b_out = (const float*)d_in[7];
    float* out = (float*)d_out;

    const int attn_smem = (4096 + 16384 + 16384) * (int)sizeof(float);  // 147456
    cudaFuncSetAttribute(k_attn, cudaFuncAttributeMaxDynamicSharedMemorySize, attn_smem);

    k_qkv <<<dim3(8, 512),  256>>>(x, wq, wk, wv);
    k_proj<<<dim3(4, 2, 64), 256>>>(E, F);
    k_attn<<<dim3(64, 64),  256, attn_smem>>>();
    k_out <<<dim3(8, 512),  256>>>(w_out, b_out, out);
}

// round 2
// speedup vs baseline: 1.1709x; 1.1709x over previous
#include <cuda_runtime.h>

#define BATCH 8
#define HEADS 8
#define SEQ 4096
#define DMODEL 512
#define DEPTH 64
#define PROJ 256
#define ROWS (BATCH*SEQ)

// Scratch (allocation-free rule: __device__ globals)
__device__ float g_q[BATCH*HEADS*SEQ*DEPTH];
__device__ float g_k[BATCH*HEADS*SEQ*DEPTH];
__device__ float g_v[BATCH*HEADS*SEQ*DEPTH];
__device__ float g_kp[BATCH*HEADS*PROJ*DEPTH];
__device__ float g_vp[BATCH*HEADS*PROJ*DEPTH];
__device__ float g_ao[ROWS*DMODEL];

// ---------------------------------------------------------------------------
// Kernel 1: QKV projection.  z selects {wq,wk,wv} -> {g_q,g_k,g_v}.
// 128x128 tile, BK=8, double-buffered, 8x8 per thread.
// Epilogue scatters to head-major [b,h,n,d].
// ---------------------------------------------------------------------------
__global__ __launch_bounds__(256, 2) void k_qkv(const float* __restrict__ x,
                                                const float* __restrict__ wq,
                                                const float* __restrict__ wk,
                                                const float* __restrict__ wv)
{
    __shared__ float As[2][8][128];
    __shared__ float Bs[2][8][128];
    const int z = blockIdx.z;
    const float* W = (z == 0) ? wq : ((z == 1) ? wk : wv);
    float* dst = (z == 0) ? g_q : ((z == 1) ? g_k : g_v);

    const int tid  = threadIdx.x;
    const int row0 = blockIdx.y * 128;
    const int col0 = blockIdx.x * 128;
    const int aRow = tid >> 1, aCol = (tid & 1) << 2;
    const int bRow = tid >> 5, bCol = (tid & 31) << 2;
    const int tm = tid >> 4, tn = tid & 15;
    float c[8][8] = {};

    const float* Aptr = x + (row0 + aRow) * DMODEL + aCol;
    const float* Bptr = W + bRow * DMODEL + col0 + bCol;

    float4 av = *(const float4*)Aptr;
    float4 bv = *(const float4*)Bptr;
    As[0][aCol+0][aRow] = av.x; As[0][aCol+1][aRow] = av.y;
    As[0][aCol+2][aRow] = av.z; As[0][aCol+3][aRow] = av.w;
    *(float4*)&Bs[0][bRow][bCol] = bv;
    __syncthreads();

    int buf = 0;
    for (int k0 = 8; ; k0 += 8) {
        const bool has = (k0 < DMODEL);
        float4 an, bn;
        if (has) {
            an = *(const float4*)(Aptr + k0);
            bn = *(const float4*)(Bptr + k0 * DMODEL);
        }
        #pragma unroll
        for (int kk = 0; kk < 8; kk++) {
            float4 a0 = *(const float4*)&As[buf][kk][tm << 2];
            float4 a1 = *(const float4*)&As[buf][kk][(tm << 2) + 64];
            float4 b0 = *(const float4*)&Bs[buf][kk][tn << 2];
            float4 b1 = *(const float4*)&Bs[buf][kk][(tn << 2) + 64];
            float ar[8] = {a0.x,a0.y,a0.z,a0.w,a1.x,a1.y,a1.z,a1.w};
            float br[8] = {b0.x,b0.y,b0.z,b0.w,b1.x,b1.y,b1.z,b1.w};
            #pragma unroll
            for (int i = 0; i < 8; i++)
                #pragma unroll
                for (int j = 0; j < 8; j++)
                    c[i][j] += ar[i] * br[j];
        }
        if (!has) break;
        As[buf^1][aCol+0][aRow] = an.x; As[buf^1][aCol+1][aRow] = an.y;
        As[buf^1][aCol+2][aRow] = an.z; As[buf^1][aCol+3][aRow] = an.w;
        *(float4*)&Bs[buf^1][bRow][bCol] = bn;
        __syncthreads();
        buf ^= 1;
    }

    #pragma unroll
    for (int ih = 0; ih < 2; ih++)
        #pragma unroll
        for (int i = 0; i < 4; i++) {
            int gr = row0 + ih * 64 + (tm << 2) + i;
            int b = gr >> 12, n = gr & (SEQ - 1);
            #pragma unroll
            for (int jh = 0; jh < 2; jh++) {
                int gc = col0 + jh * 64 + (tn << 2);
                int h = gc >> 6, d = gc & 63;
                float4 v;
                v.x = c[ih*4+i][jh*4+0]; v.y = c[ih*4+i][jh*4+1];
                v.z = c[ih*4+i][jh*4+2]; v.w = c[ih*4+i][jh*4+3];
                *(float4*)&dst[((b * HEADS + h) * SEQ + n) * DEPTH + d] = v;
            }
        }
}

// ---------------------------------------------------------------------------
// Kernel 2: low-rank projection.  kp[r,d] = sum_n E[h][n][r] * k[bh][n][d].
// 64x64 tile, BK=16, double-buffered, 4x4 per thread (both operands K-major).
// ---------------------------------------------------------------------------
__global__ __launch_bounds__(256, 2) void k_proj(const float* __restrict__ E,
                                                 const float* __restrict__ F)
{
    const int bh    = blockIdx.z;
    const int h     = bh & 7;
    const int which = blockIdx.y;
    const int r0    = blockIdx.x * 64;
    const float* A  = (which ? F : E) + h * SEQ * PROJ;
    const float* Bm = (which ? g_v : g_k) + bh * SEQ * DEPTH;
    float*       C  = (which ? g_vp : g_kp) + bh * PROJ * DEPTH;

    __shared__ float As[2][16][64];
    __shared__ float Bs[2][16][64];
    const int tid = threadIdx.x;
    const int lRow = tid >> 4, lCol = (tid & 15) << 2;
    const int tm = tid >> 4, tn = tid & 15;
    float c[4][4] = {};

    const float* Aptr = A + lRow * PROJ + r0 + lCol;
    const float* Bptr = Bm + lRow * DEPTH + lCol;

    *(float4*)&As[0][lRow][lCol] = *(const float4*)Aptr;
    *(float4*)&Bs[0][lRow][lCol] = *(const float4*)Bptr;
    __syncthreads();

    int buf = 0;
    for (int k0 = 16; ; k0 += 16) {
        const bool has = (k0 < SEQ);
        float4 an, bn;
        if (has) {
            an = *(const float4*)(Aptr + k0 * PROJ);
            bn = *(const float4*)(Bptr + k0 * DEPTH);
        }
        #pragma unroll
        for (int kk = 0; kk < 16; kk++) {
            float4 a4 = *(const float4*)&As[buf][kk][tm << 2];
            float4 b4 = *(const float4*)&Bs[buf][kk][tn << 2];
            float ar[4] = {a4.x,a4.y,a4.z,a4.w};
            float br[4] = {b4.x,b4.y,b4.z,b4.w};
            #pragma unroll
            for (int i = 0; i < 4; i++)
                #pragma unroll
                for (int j = 0; j < 4; j++)
                    c[i][j] += ar[i] * br[j];
        }
        if (!has) break;
        *(float4*)&As[buf^1][lRow][lCol] = an;
        *(float4*)&Bs[buf^1][lRow][lCol] = bn;
        __syncthreads();
        buf ^= 1;
    }

    #pragma unroll
    for (int i = 0; i < 4; i++) {
        float4 v;
        v.x = c[i][0]; v.y = c[i][1]; v.z = c[i][2]; v.w = c[i][3];
        *(float4*)&C[(r0 + (tm << 2) + i) * DEPTH + (tn << 2)] = v;
    }
}

// ---------------------------------------------------------------------------
// Kernel 3: fused attention per (bh, 64-row tile).
// GEMM1 (S=Q@Kp^T): Q staged transposed (pad 68) -> 4 LDS.128 / 64 FFMA.
// Softmax: warp-local (each warp owns 8 rows, cols spread across lanes).
// GEMM2 (O=P@Vp): K unrolled by 4 -> 8 LDS.128 / 64 FFMA.
// ---------------------------------------------------------------------------
#define QSTRIDE 68
__global__ __launch_bounds__(256) void k_attn()
{
    extern __shared__ float sm[];
    float* sQT  = sm;                            // 64*68 = 4352 floats [d][m]
    float* sKpT = sm + 64*QSTRIDE;               // 64*256 floats [d][r]; reused as sP[m][r]
    float* sVp  = sm + 64*QSTRIDE + 64*PROJ;     // 256*64 floats [r][d]

    const int bh = blockIdx.y;
    const int m0 = blockIdx.x * 64;
    const float* Q  = g_q  + (bh * SEQ + m0) * DEPTH;
    const float* Kp = g_kp + bh * PROJ * DEPTH;
    const float* Vp = g_vp + bh * PROJ * DEPTH;
    const int tid = threadIdx.x, lane = tid & 31, wy = tid >> 5;

    // Stage Q transposed: lanes cover distinct m -> conflict-free scalar stores
    #pragma unroll
    for (int it = 0; it < 4; it++) {
        int idx = tid + it * 256;
        int m = idx & 63, d4 = (idx >> 6) << 2;
        float4 qv = *(const float4*)&Q[m * DEPTH + d4];
        sQT[(d4+0)*QSTRIDE + m] = qv.x;
        sQT[(d4+1)*QSTRIDE + m] = qv.y;
        sQT[(d4+2)*QSTRIDE + m] = qv.z;
        sQT[(d4+3)*QSTRIDE + m] = qv.w;
    }
    // Stage Kp transposed: thread j owns row j -> writes column j (conflict-free)
    {
        const int j = tid;
        #pragma unroll
        for (int d0 = 0; d0 < DEPTH; d0 += 4) {
            float4 kv = *(const float4*)&Kp[j * DEPTH + d0];
            sKpT[(d0+0)*PROJ + j] = kv.x;
            sKpT[(d0+1)*PROJ + j] = kv.y;
            sKpT[(d0+2)*PROJ + j] = kv.z;
            sKpT[(d0+3)*PROJ + j] = kv.w;
        }
    }
    for (int i = tid; i < 4096; i += 256)
        *(float4*)&sVp[i*4] = *(const float4*)&Vp[i*4];
    __syncthreads();

    // GEMM1: warp wy owns rows mBase..mBase+7; lane owns cols lane*4 (+128)
    const int mBase = wy * 8;
    const int cBase = lane << 2;
    float s[8][8];
    #pragma unroll
    for (int i = 0; i < 8; i++)
        #pragma unroll
        for (int j = 0; j < 8; j++) s[i][j] = 0.f;

    #pragma unroll 8
    for (int kk = 0; kk < DEPTH; kk++) {
        float4 a0 = *(const float4*)&sQT[kk*QSTRIDE + mBase];
        float4 a1 = *(const float4*)&sQT[kk*QSTRIDE + mBase + 4];
        float4 b0 = *(const float4*)&sKpT[kk*PROJ + cBase];
        float4 b1 = *(const float4*)&sKpT[kk*PROJ + cBase + 128];
        float ar[8] = {a0.x,a0.y,a0.z,a0.w,a1.x,a1.y,a1.z,a1.w};
        float br[8] = {b0.x,b0.y,b0.z,b0.w,b1.x,b1.y,b1.z,b1.w};
        #pragma unroll
        for (int i = 0; i < 8; i++)
            #pragma unroll
            for (int j = 0; j < 8; j++)
                s[i][j] += ar[i] * br[j];
    }

    // Softmax per row (row fully within one warp)
    const float scale = 0.125f;
    #pragma unroll
    for (int i = 0; i < 8; i++) {
        float mx = -1e30f;
        #pragma unroll
        for (int j = 0; j < 8; j++) { s[i][j] *= scale; mx = fmaxf(mx, s[i][j]); }
        #pragma unroll
        for (int off = 16; off > 0; off >>= 1)
            mx = fmaxf(mx, __shfl_xor_sync(0xffffffff, mx, off));
        float sum = 0.f;
        #pragma unroll
        for (int j = 0; j < 8; j++) { s[i][j] = __expf(s[i][j] - mx); sum += s[i][j]; }
        #pragma unroll
        for (int off = 16; off > 0; off >>= 1)
            sum += __shfl_xor_sync(0xffffffff, sum, off);
        float inv = 1.0f / sum;
        #pragma unroll
        for (int j = 0; j < 8; j++) s[i][j] *= inv;
    }

    __syncthreads();          // all warps done reading sKpT
    float* sP = sKpT;         // reuse as P[m][r], row-major
    #pragma unroll
    for (int i = 0; i < 8; i++) {
        float4 v0, v1;
        v0.x = s[i][0]; v0.y = s[i][1]; v0.z = s[i][2]; v0.w = s[i][3];
        v1.x = s[i][4]; v1.y = s[i][5]; v1.z = s[i][6]; v1.w = s[i][7];
        *(float4*)&sP[(mBase+i)*PROJ + cBase]       = v0;
        *(float4*)&sP[(mBase+i)*PROJ + cBase + 128] = v1;
    }
    __syncthreads();

    // GEMM2: O[64][64] = P[64][256] @ Vp[256][64], K unrolled by 4
    const int tm = tid >> 4, tn = tid & 15;
    float o[4][4] = {};
    #pragma unroll 4
    for (int k0 = 0; k0 < PROJ; k0 += 4) {
        float aa[4][4], bb[4][4];
        #pragma unroll
        for (int i = 0; i < 4; i++) {
            float4 a = *(const float4*)&sP[(tm*4+i)*PROJ + k0];
            aa[i][0]=a.x; aa[i][1]=a.y; aa[i][2]=a.z; aa[i][3]=a.w;
        }
        #pragma unroll
        for (int q = 0; q < 4; q++) {
            float4 b = *(const float4*)&sVp[(k0+q)*DEPTH + (tn << 2)];
            bb[q][0]=b.x; bb[q][1]=b.y; bb[q][2]=b.z; bb[q][3]=b.w;
        }
        #pragma unroll
        for (int i = 0; i < 4; i++)
            #pragma unroll
            for (int q = 0; q < 4; q++)
                #pragma unroll
                for (int j = 0; j < 4; j++)
                    o[i][j] += aa[i][q] * bb[q][j];
    }

    const int b = bh >> 3, h = bh & 7;
    #pragma unroll
    for (int i = 0; i < 4; i++) {
        int n = m0 + tm*4 + i;
        float4 v;
        v.x = o[i][0]; v.y = o[i][1]; v.z = o[i][2]; v.w = o[i][3];
        *(float4*)&g_ao[(b * SEQ + n) * DMODEL + h * DEPTH + (tn << 2)] = v;
    }
}

// ---------------------------------------------------------------------------
// Kernel 4: output projection.  out = ao @ w_out + b_out.  Same SGEMM shape.
// ---------------------------------------------------------------------------
__global__ __launch_bounds__(256, 2) void k_out(const float* __restrict__ w,
                                                const float* __restrict__ bias,
                                                float* __restrict__ out)
{
    __shared__ float As[2][8][128];
    __shared__ float Bs[2][8][128];
    const int tid  = threadIdx.x;
    const int row0 = blockIdx.y * 128;
    const int col0 = blockIdx.x * 128;
    const int aRow = tid >> 1, aCol = (tid & 1) << 2;
    const int bRow = tid >> 5, bCol = (tid & 31) << 2;
    const int tm = tid >> 4, tn = tid & 15;
    float c[8][8] = {};

    const float* Aptr = g_ao + (row0 + aRow) * DMODEL + aCol;
    const float* Bptr = w + bRow * DMODEL + col0 + bCol;

    float4 av = *(const float4*)Aptr;
    float4 bv = *(const float4*)Bptr;
    As[0][aCol+0][aRow] = av.x; As[0][aCol+1][aRow] = av.y;
    As[0][aCol+2][aRow] = av.z; As[0][aCol+3][aRow] = av.w;
    *(float4*)&Bs[0][bRow][bCol] = bv;
    __syncthreads();

    int buf = 0;
    for (int k0 = 8; ; k0 += 8) {
        const bool has = (k0 < DMODEL);
        float4 an, bn;
        if (has) {
            an = *(const float4*)(Aptr + k0);
            bn = *(const float4*)(Bptr + k0 * DMODEL);
        }
        #pragma unroll
        for (int kk = 0; kk < 8; kk++) {
            float4 a0 = *(const float4*)&As[buf][kk][tm << 2];
            float4 a1 = *(const float4*)&As[buf][kk][(tm << 2) + 64];
            float4 b0 = *(const float4*)&Bs[buf][kk][tn << 2];
            float4 b1 = *(const float4*)&Bs[buf][kk][(tn << 2) + 64];
            float ar[8] = {a0.x,a0.y,a0.z,a0.w,a1.x,a1.y,a1.z,a1.w};
            float br[8] = {b0.x,b0.y,b0.z,b0.w,b1.x,b1.y,b1.z,b1.w};
            #pragma unroll
            for (int i = 0; i < 8; i++)
                #pragma unroll
                for (int j = 0; j < 8; j++)
                    c[i][j] += ar[i] * br[j];
        }
        if (!has) break;
        As[buf^1][aCol+0][aRow] = an.x; As[buf^1][aCol+1][aRow] = an.y;
        As[buf^1][aCol+2][aRow] = an.z; As[buf^1][aCol+3][aRow] = an.w;
        *(float4*)&Bs[buf^1][bRow][bCol] = bn;
        __syncthreads();
        buf ^= 1;
    }

    #pragma unroll
    for (int ih = 0; ih < 2; ih++)
        #pragma unroll
        for (int i = 0; i < 4; i++) {
            int gr = row0 + ih * 64 + (tm << 2) + i;
            #pragma unroll
            for (int jh = 0; jh < 2; jh++) {
                int gc = col0 + jh * 64 + (tn << 2);
                float4 bsv = *(const float4*)&bias[gc];
                float4 v;
                v.x = c[ih*4+i][jh*4+0] + bsv.x;
                v.y = c[ih*4+i][jh*4+1] + bsv.y;
                v.z = c[ih*4+i][jh*4+2] + bsv.z;
                v.w = c[ih*4+i][jh*4+3] + bsv.w;
                *(float4*)&out[gr * DMODEL + gc] = v;
            }
        }
}

// ---------------------------------------------------------------------------
extern "C" void kernel_launch(void* const* d_in, const int* in_sizes, int n_in,
                              void* d_out, int out_size)
{
    (void)in_sizes; (void)n_in; (void)out_size;
    const float* x     = (const float*)d_in[0];
    const float* wq    = (const float*)d_in[1];
    const float* wk    = (const float*)d_in[2];
    const float* wv    = (const float*)d_in[3];
    const float* E     = (const float*)d_in[4];
    const float* F     = (const float*)d_in[5];
    const float* w_out = (const float*)d_in[6];
    const float* b_out = (const float*)d_in[7];
    float* out = (float*)d_out;

    const int attn_smem = (64*QSTRIDE + 64*PROJ + PROJ*64) * (int)sizeof(float); // 148480
    cudaFuncSetAttribute(k_attn, cudaFuncAttributeMaxDynamicSharedMemorySize, attn_smem);

    k_qkv <<<dim3(4, 256, 3), 256>>>(x, wq, wk, wv);
    k_proj<<<dim3(4, 2, 64),  256>>>(E, F);
    k_attn<<<dim3(64, 64),    256, attn_smem>>>();
    k_out <<<dim3(4, 256),    256>>>(w_out, b_out, out);
}